// round 17
// baseline (speedup 1.0000x reference)
#include <cuda_runtime.h>
#include <cstdint>

#define Tn 2048

__device__ __forceinline__ uint32_t smem_u32(const void* p) {
    return (uint32_t)__cvta_generic_to_shared(p);
}
__device__ __forceinline__ void cluster_sync_() {
    asm volatile("barrier.cluster.arrive.aligned;" ::: "memory");
    asm volatile("barrier.cluster.wait.aligned;" ::: "memory");
}
__device__ __forceinline__ uint32_t mapa_sh(uint32_t addr, uint32_t rank) {
    uint32_t r;
    asm("mapa.shared::cluster.u32 %0, %1, %2;" : "=r"(r) : "r"(addr), "r"(rank));
    return r;
}
__device__ __forceinline__ void mbar_init(uint32_t a, uint32_t cnt) {
    asm volatile("mbarrier.init.shared.b64 [%0], %1;" :: "r"(a), "r"(cnt) : "memory");
}
__device__ __forceinline__ void mbar_arm_tx(uint32_t a, uint32_t tx) {
    asm volatile("mbarrier.arrive.expect_tx.shared.b64 _, [%0], %1;"
                 :: "r"(a), "r"(tx) : "memory");
}
__device__ __forceinline__ void mbar_wait_cl(uint32_t a, uint32_t parity) {
    asm volatile(
        "{\n\t.reg .pred P;\n\t"
        "WL_%=:\n\t"
        "mbarrier.try_wait.parity.acquire.cluster.shared::cta.b64 P, [%0], %1, 0x989680;\n\t"
        "@P bra.uni WD_%=;\n\t"
        "bra.uni WL_%=;\n\t"
        "WD_%=:\n\t}"
        :: "r"(a), "r"(parity) : "memory");
}
__device__ __forceinline__ void bulk_dsmem(uint32_t dst, uint32_t src,
                                           uint32_t bytes, uint32_t mbar) {
    asm volatile(
        "cp.async.bulk.shared::cluster.shared::cta.mbarrier::complete_tx::bytes "
        "[%0], [%1], %2, [%3];"
        :: "r"(dst), "r"(src), "r"(bytes), "r"(mbar) : "memory");
}
__device__ __forceinline__ void fence_async_() {
    asm volatile("fence.proxy.async.shared::cta;" ::: "memory");
}
__device__ __forceinline__ float sigm(float v) { return 1.0f / (1.0f + __expf(-v)); }
__device__ __forceinline__ float tanh_(float v) { return 2.0f / (1.0f + __expf(-2.0f * v)) - 1.0f; }

__device__ __forceinline__ unsigned long long pk2(float v) {
    unsigned long long r;
    asm("mov.b64 %0, {%1, %1};" : "=l"(r) : "f"(v));
    return r;
}
__device__ __forceinline__ void ffma2(unsigned long long& d, unsigned long long a,
                                      unsigned long long b) {
    asm("fma.rn.f32x2 %0, %1, %2, %0;" : "+l"(d) : "l"(a), "l"(b));
}
__device__ __forceinline__ void unpk(unsigned long long v, float& lo, float& hi) {
    asm("mov.b64 {%0, %1}, %2;" : "=f"(lo), "=f"(hi) : "l"(v));
}
__device__ __forceinline__ float sel4(float4 v, int s) {
    return (s == 0) ? v.x : (s == 1) ? v.y : (s == 2) ? v.z : v.w;
}

// ---------------------------------------------------------------------------
// FUSED pipelined kernel: cluster of 4 CTAs x 512 threads, 8 batches/cluster,
// 32 clusters = 128 CTAs. At step t the CTA computes h1(t) AND h2(t-1):
// both inputs (h1(t-1), h2(t-2)) were shipped at step t-1 -> no intra-step
// cross-layer dependency (this is the fix for the round-10 lockstep failure).
// Thread = (row-pair rp in [0,64), seg in [0,8)): L0 window = (seg&3)*32 +
// (seg>>2)*16 (16 j), L1 window = (seg&3)*32 (32 j; seg<4 -> W_ih1 over h1,
// seg>=4 -> W_hh1 over h2). m = seg&3 = the single h1 source this thread
// reads; own-rank slices come from local stage (no wait). Per-source parity
// mbars (h1 @bytes 0-63, h2 @64-127); phases: h1 (t>>1)&1, h2 ((t-1)>>1)&1
// (h2 only buffer-1 primed). Combine split: tid<256 -> L0, tid>=256 -> L1.
// smem floats: mbars @0 (32), h1buf [2][128][8] @32, h2buf @2080,
//   st1 [2][256] @4128, st2 [2][256] @4640, xbf [2][5][8] @5152,
//   gb0 [8][128][9] @5232, gb1 @14448, wxs [128][5] @23664,
//   bb0s @24304, bb1s @24432 -> 24560 floats = 98240 B
// ---------------------------------------------------------------------------
#define H1B  32
#define H2B  2080
#define ST1f 4128
#define ST2f 4640
#define XBFf 5152
#define GB0f 5232
#define GB1f 14448
#define WXSf 23664
#define BB0f 24304
#define BB1f 24432
#define SMEM_BYTES (24560 * 4)

__global__ void __cluster_dims__(4, 1, 1) __launch_bounds__(512, 1)
lstm_fused(const float* __restrict__ x,
           const float* __restrict__ Wih0, const float* __restrict__ Whh0,
           const float* __restrict__ bih0, const float* __restrict__ bhh0,
           const float* __restrict__ Wih1, const float* __restrict__ Whh1,
           const float* __restrict__ bih1, const float* __restrict__ bhh1,
           const float* __restrict__ fcW, const float* __restrict__ fcb,
           float* __restrict__ out)
{
    extern __shared__ float sm[];
    const uint32_t smb = smem_u32(sm);
    float* h1buf = sm + H1B;
    float* h2buf = sm + H2B;
    float* st1   = sm + ST1f;
    float* st2   = sm + ST2f;
    float* xbf   = sm + XBFf;
    float* gb0   = sm + GB0f;
    float* gb1   = sm + GB1f;
    float* wxs   = sm + WXSf;
    float* bb0s  = sm + BB0f;
    float* bb1s  = sm + BB1f;

    const int tid  = threadIdx.x;
    const int rank = blockIdx.x & 3;
    const int b0   = (blockIdx.x >> 2) * 8;

    const int seg = tid >> 6;            // 0..7
    const int rp  = tid & 63;
    const int r0  = rp, r1 = rp + 64;    // two gate rows per thread
    const int m   = seg & 3;             // source slice index
    const int gr0 = ((r0 >> 5) << 7) + (rank << 5) + (r0 & 31);
    const int gr1 = ((r1 >> 5) << 7) + (rank << 5) + (r1 & 31);

    // L0 weights: Whh0 cols [m*32 + (seg>>2)*16, +16), 2 rows (32 floats)
    float4 w0a[4], w0b[4];
    {
        const int c0 = m * 32 + (seg >> 2) * 16;
        const float4* s0 = (const float4*)(Whh0 + gr0 * 128 + c0);
        const float4* s1 = (const float4*)(Whh0 + gr1 * 128 + c0);
        #pragma unroll
        for (int kk = 0; kk < 4; ++kk) { w0a[kk] = s0[kk]; w0b[kk] = s1[kk]; }
    }
    // L1 weights: seg<4 -> Wih1, seg>=4 -> Whh1; cols [m*32, +32) (64 floats)
    float4 w1a[8], w1b[8];
    {
        const float* wm = (seg < 4) ? Wih1 : Whh1;
        const float4* s0 = (const float4*)(wm + gr0 * 128 + m * 32);
        const float4* s1 = (const float4*)(wm + gr1 * 128 + m * 32);
        #pragma unroll
        for (int kk = 0; kk < 8; ++kk) { w1a[kk] = s0[kk]; w1b[kk] = s1[kk]; }
    }

    if (tid == 0) {   // 16 mbars: h1[2][4] @0, h2[2][4] @64; arm src != rank
        #pragma unroll
        for (int p = 0; p < 2; ++p)
            #pragma unroll
            for (int s = 0; s < 4; ++s) {
                mbar_init(smb + p * 32 + s * 8, 1);
                mbar_init(smb + 64 + p * 32 + s * 8, 1);
                if (s != rank) {
                    mbar_arm_tx(smb + p * 32 + s * 8, 1024);
                    mbar_arm_tx(smb + 64 + p * 32 + s * 8, 1024);
                }
            }
    }
    if (tid < 128) {   // bias tables + W_ih0 (K=5) in smem
        int gr = ((tid >> 5) << 7) + (rank << 5) + (tid & 31);
        bb0s[tid] = bih0[gr] + bhh0[gr];
        bb1s[tid] = bih1[gr] + bhh1[gr];
        #pragma unroll
        for (int d = 0; d < 5; ++d) wxs[tid * 5 + d] = Wih0[gr * 5 + d];
    }
    st1[tid] = 0.f;    // both parities of both stages zeroed (h(-1) = 0)
    st2[tid] = 0.f;
    if (tid < 40) {
        int b = tid / 5, d = tid % 5;
        xbf[d * 8 + b] = x[((size_t)(b0 + b) * Tn) * 5 + d];
    }
    uint32_t base[4];
    #pragma unroll
    for (int r = 0; r < 4; ++r) base[r] = mapa_sh(smb, r);

    __syncthreads();
    cluster_sync_();   // mbars armed + zeroed stages visible cluster-wide
    if (tid < 3) {     // primes: h1(-1)=0 -> h1buf[0]; h2(-1)=0 -> h2buf[1]
        int dr = tid + (tid >= rank);
        fence_async_();
        bulk_dsmem(base[dr] + (H1B + rank * 256) * 4, smb + ST1f * 4,
                   1024, base[dr] + rank * 8);
        bulk_dsmem(base[dr] + (H2B + 1024 + rank * 256) * 4, smb + ST2f * 4,
                   1024, base[dr] + 64 + 32 + rank * 8);
    }

    float cst = 0.f;   // LSTM cell state: L0's c for tid<256, L1's c for tid>=256

    for (int t = 0; t <= Tn; ++t) {
        const int par = t & 1, nb = par ^ 1;
        float pre = 0.f;
        if (tid < 40 && t + 1 < Tn)
            pre = x[((size_t)(b0 + tid / 5) * Tn + (t + 1)) * 5 + (tid % 5)];

        // ---- waits: both inputs were shipped at step t-1 ----
        if (m != rank) {
            uint32_t mb = smb + par * 32 + m * 8;        // h1(t-1) slice m
            mbar_wait_cl(mb, (t >> 1) & 1);
            if (tid == m * 64) mbar_arm_tx(mb, 1024);
        }
        if (seg >= 4 && m != rank && t >= 1) {
            uint32_t mb = smb + 64 + par * 32 + m * 8;   // h2(t-2) slice m
            mbar_wait_cl(mb, ((t - 1) >> 1) & 1);
            if (rp == 0) mbar_arm_tx(mb, 1024);
        }

        // ---- L0 compute: gates of h1(t) from h1(t-1) ----
        if (t < Tn) {
            unsigned long long a0[4], a1[4];
            #pragma unroll
            for (int i = 0; i < 4; ++i) { a0[i] = 0ull; a1[i] = 0ull; }
            if (seg == 0) {   // x-projection (seg0's rows cover all 128 rows)
                const float* xb = xbf + par * 40;
                #pragma unroll
                for (int d = 0; d < 5; ++d) {
                    unsigned long long wv0 = pk2(wxs[r0 * 5 + d]);
                    unsigned long long wv1 = pk2(wxs[r1 * 5 + d]);
                    const unsigned long long* xp =
                        (const unsigned long long*)(xb + d * 8);
                    #pragma unroll
                    for (int i = 0; i < 4; ++i) {
                        ffma2(a0[i], wv0, xp[i]);
                        ffma2(a1[i], wv1, xp[i]);
                    }
                }
            }
            const float* src = ((m == rank) ? (st1 + par * 256)
                                            : (h1buf + par * 1024 + m * 256))
                               + (seg >> 2) * 128;
            #pragma unroll
            for (int kk = 0; kk < 4; ++kk) {
                float4 wv0 = w0a[kk], wv1 = w0b[kk];
                #pragma unroll
                for (int s = 0; s < 4; ++s) {
                    const float* p = src + (kk * 4 + s) * 8;
                    ulonglong2 hA = *(const ulonglong2*)(p);
                    ulonglong2 hB = *(const ulonglong2*)(p + 4);
                    unsigned long long pw = pk2(sel4(wv0, s));
                    ffma2(a0[0], pw, hA.x); ffma2(a0[1], pw, hA.y);
                    ffma2(a0[2], pw, hB.x); ffma2(a0[3], pw, hB.y);
                    pw = pk2(sel4(wv1, s));
                    ffma2(a1[0], pw, hA.x); ffma2(a1[1], pw, hA.y);
                    ffma2(a1[2], pw, hB.x); ffma2(a1[3], pw, hB.y);
                }
            }
            float* gp = gb0 + seg * 1152;
            float v0, v1;
            #pragma unroll
            for (int i = 0; i < 4; ++i) {
                unpk(a0[i], v0, v1);
                gp[r0 * 9 + i * 2] = v0; gp[r0 * 9 + i * 2 + 1] = v1;
            }
            #pragma unroll
            for (int i = 0; i < 4; ++i) {
                unpk(a1[i], v0, v1);
                gp[r1 * 9 + i * 2] = v0; gp[r1 * 9 + i * 2 + 1] = v1;
            }
        }

        // ---- L1 compute: gates of h2(t-1) from h1(t-1) & h2(t-2) ----
        if (t >= 1) {
            unsigned long long a0[4], a1[4];
            #pragma unroll
            for (int i = 0; i < 4; ++i) { a0[i] = 0ull; a1[i] = 0ull; }
            const float* src = (seg < 4)
                ? ((m == rank) ? (st1 + par * 256) : (h1buf + par * 1024 + m * 256))
                : ((m == rank) ? (st2 + par * 256) : (h2buf + par * 1024 + m * 256));
            #pragma unroll
            for (int kk = 0; kk < 8; ++kk) {
                float4 wv0 = w1a[kk], wv1 = w1b[kk];
                #pragma unroll
                for (int s = 0; s < 4; ++s) {
                    const float* p = src + (kk * 4 + s) * 8;
                    ulonglong2 hA = *(const ulonglong2*)(p);
                    ulonglong2 hB = *(const ulonglong2*)(p + 4);
                    unsigned long long pw = pk2(sel4(wv0, s));
                    ffma2(a0[0], pw, hA.x); ffma2(a0[1], pw, hA.y);
                    ffma2(a0[2], pw, hB.x); ffma2(a0[3], pw, hB.y);
                    pw = pk2(sel4(wv1, s));
                    ffma2(a1[0], pw, hA.x); ffma2(a1[1], pw, hA.y);
                    ffma2(a1[2], pw, hB.x); ffma2(a1[3], pw, hB.y);
                }
            }
            float* gp = gb1 + seg * 1152;
            float v0, v1;
            #pragma unroll
            for (int i = 0; i < 4; ++i) {
                unpk(a0[i], v0, v1);
                gp[r0 * 9 + i * 2] = v0; gp[r0 * 9 + i * 2 + 1] = v1;
            }
            #pragma unroll
            for (int i = 0; i < 4; ++i) {
                unpk(a1[i], v0, v1);
                gp[r1 * 9 + i * 2] = v0; gp[r1 * 9 + i * 2 + 1] = v1;
            }
        }
        if (tid < 40 && t + 1 < Tn)
            xbf[nb * 40 + (tid % 5) * 8 + (tid / 5)] = pre;
        __syncthreads();   // bar1: gate partials ready

        if (tid < 256) {
            if (t < Tn) {   // ---- L0 combine -> h1(t), ship ----
                const int cb = tid & 7, cj = tid >> 3;
                float gv[4];
                #pragma unroll
                for (int g = 0; g < 4; ++g) {
                    int off = (g * 32 + cj) * 9 + cb;
                    float s01 = gb0[off] + gb0[1152 + off];
                    float s23 = gb0[2304 + off] + gb0[3456 + off];
                    float s45 = gb0[4608 + off] + gb0[5760 + off];
                    float s67 = gb0[6912 + off] + gb0[8064 + off];
                    gv[g] = bb0s[g * 32 + cj] + ((s01 + s23) + (s45 + s67));
                }
                float ii = sigm(gv[0]), ff = sigm(gv[1]);
                float gg = tanh_(gv[2]), oo = sigm(gv[3]);
                cst = fmaf(ff, cst, ii * gg);
                float h = oo * tanh_(cst);
                st1[nb * 256 + tid] = h;
                __syncwarp();
                if ((tid & 31) < 3) {
                    int l = tid & 31, dr = l + (l >= rank);
                    fence_async_();
                    bulk_dsmem(base[dr] + (H1B + nb * 1024 + rank * 256 + (tid & 224)) * 4,
                               smb + (ST1f + nb * 256 + (tid & 224)) * 4, 128,
                               base[dr] + nb * 32 + rank * 8);
                }
            }
        } else {
            if (t >= 1) {   // ---- L1 combine -> h2(t-1), ship ----
                const int ct = tid - 256;
                const int cb = ct & 7, cj = ct >> 3;
                float gv[4];
                #pragma unroll
                for (int g = 0; g < 4; ++g) {
                    int off = (g * 32 + cj) * 9 + cb;
                    float s01 = gb1[off] + gb1[1152 + off];
                    float s23 = gb1[2304 + off] + gb1[3456 + off];
                    float s45 = gb1[4608 + off] + gb1[5760 + off];
                    float s67 = gb1[6912 + off] + gb1[8064 + off];
                    gv[g] = bb1s[g * 32 + cj] + ((s01 + s23) + (s45 + s67));
                }
                float ii = sigm(gv[0]), ff = sigm(gv[1]);
                float gg = tanh_(gv[2]), oo = sigm(gv[3]);
                cst = fmaf(ff, cst, ii * gg);
                float h = oo * tanh_(cst);
                st2[nb * 256 + ct] = h;
                __syncwarp();
                if ((ct & 31) < 3) {
                    int l = ct & 31, dr = l + (l >= rank);
                    fence_async_();
                    bulk_dsmem(base[dr] + (H2B + nb * 1024 + rank * 256 + (ct & 224)) * 4,
                               smb + (ST2f + nb * 256 + (ct & 224)) * 4, 128,
                               base[dr] + 64 + nb * 32 + rank * 8);
                }
            }
        }
        __syncthreads();   // bar2: stages/gbufs safe for next step
    }

    // consume the final h2 ships (t=Tn -> h2buf[1], phase 0): exit safety +
    // final h2 visible for the FC head
    if (tid < 4 && tid != rank)
        mbar_wait_cl(smb + 64 + 32 + tid * 8, 0);
    __syncthreads();

    // FC head: final h2(Tn-1) = own slice in st2[1], remote slices in h2buf[1]
    if (rank == 0 && tid < 16) {
        int b = tid >> 1, cl = tid & 1;
        float s = fcb[cl];
        #pragma unroll
        for (int j = 0; j < 128; ++j) {
            float hv = ((j >> 5) == rank) ? st2[256 + (j & 31) * 8 + b]
                                          : h2buf[1024 + j * 8 + b];
            s = fmaf(hv, fcW[cl * 128 + j], s);
        }
        out[(b0 + b) * 2 + cl] = s;
    }
}

// ---------------------------------------------------------------------------
extern "C" void kernel_launch(void* const* d_in, const int* in_sizes, int n_in,
                              void* d_out, int out_size)
{
    const float* x    = (const float*)d_in[0];
    const float* Wih0 = (const float*)d_in[1];
    const float* Whh0 = (const float*)d_in[2];
    const float* bih0 = (const float*)d_in[3];
    const float* bhh0 = (const float*)d_in[4];
    const float* Wih1 = (const float*)d_in[5];
    const float* Whh1 = (const float*)d_in[6];
    const float* bih1 = (const float*)d_in[7];
    const float* bhh1 = (const float*)d_in[8];
    const float* fcW  = (const float*)d_in[9];
    const float* fcb  = (const float*)d_in[10];
    float* out = (float*)d_out;

    cudaFuncSetAttribute(lstm_fused, cudaFuncAttributeMaxDynamicSharedMemorySize,
                         SMEM_BYTES);
    lstm_fused<<<128, 512, SMEM_BYTES>>>(x, Wih0, Whh0, bih0, bhh0,
                                         Wih1, Whh1, bih1, bhh1, fcW, fcb, out);
}